// round 1
// baseline (speedup 1.0000x reference)
#include <cuda_runtime.h>
#include <cuda_bf16.h>

// Upscale_15358803050749: upfirdn2d up=2, 4x4 kernel, gain UP^2.
// x: (8,128,128,128) f32 -> out: (8,128,256,256) f32.
//
// Polyphase decomposition (derived from the reference's dilated conv with
// flipped kernel, pad0=2, pad1+UP-1=2):
//   out[2i]   = K[3]*x[i-1] + K[1]*x[i]
//   out[2i+1] = K[2]*x[i]   + K[0]*x[i+1]
// separably in y and x, with zero outside [0,H)x[0,W).
//
// Thread layout: each thread handles 4 input columns of 1 input row
// (float4 + 2 halo scalars, 3 rows), producing a 2-row x 8-col output block
// written as 4x float4.

#define W_IN  128
#define H_IN  128
#define W_OUT 256
#define H_OUT 256
#define NC    1024           // 8 * 128 planes

__global__ __launch_bounds__(256)
void Upscale_15358803050749_kernel(const float* __restrict__ x,
                                   const float* __restrict__ k,
                                   float* __restrict__ out) {
    int t  = blockIdx.x * blockDim.x + threadIdx.x;
    int tx = t & 31;          // column-group 0..31 (4 input cols each)
    int r  = t >> 5;          // global input row index 0..NC*H_IN-1
    int iy = r & (H_IN - 1);
    int pl = r >> 7;          // plane index 0..NC-1
    if (pl >= NC) return;

    const float* xp = x   + (size_t)pl * (H_IN * W_IN);
    float*       op = out + (size_t)pl * (H_OUT * W_OUT);
    int ix0 = tx * 4;

    // Filter weights (uniform broadcast loads; L1-resident).
    float K00 = __ldg(k + 0),  K01 = __ldg(k + 1),  K02 = __ldg(k + 2),  K03 = __ldg(k + 3);
    float K10 = __ldg(k + 4),  K11 = __ldg(k + 5),  K12 = __ldg(k + 6),  K13 = __ldg(k + 7);
    float K20 = __ldg(k + 8),  K21 = __ldg(k + 9),  K22 = __ldg(k + 10), K23 = __ldg(k + 11);
    float K30 = __ldg(k + 12), K31 = __ldg(k + 13), K32 = __ldg(k + 14), K33 = __ldg(k + 15);

    // Load 3 input rows, local cols [ix0-1 .. ix0+4] (6 values, zero-padded).
    float rm[6], rc[6], rp[6];
    {
        // center row (always valid)
        const float* rowp = xp + (size_t)iy * W_IN;
        float4 v = *reinterpret_cast<const float4*>(rowp + ix0);
        rc[1] = v.x; rc[2] = v.y; rc[3] = v.z; rc[4] = v.w;
        rc[0] = (ix0 > 0)          ? __ldg(rowp + ix0 - 1) : 0.f;
        rc[5] = (ix0 + 4 < W_IN)   ? __ldg(rowp + ix0 + 4) : 0.f;
    }
    if (iy > 0) {
        const float* rowp = xp + (size_t)(iy - 1) * W_IN;
        float4 v = *reinterpret_cast<const float4*>(rowp + ix0);
        rm[1] = v.x; rm[2] = v.y; rm[3] = v.z; rm[4] = v.w;
        rm[0] = (ix0 > 0)          ? __ldg(rowp + ix0 - 1) : 0.f;
        rm[5] = (ix0 + 4 < W_IN)   ? __ldg(rowp + ix0 + 4) : 0.f;
    } else {
        #pragma unroll
        for (int i = 0; i < 6; i++) rm[i] = 0.f;
    }
    if (iy < H_IN - 1) {
        const float* rowp = xp + (size_t)(iy + 1) * W_IN;
        float4 v = *reinterpret_cast<const float4*>(rowp + ix0);
        rp[1] = v.x; rp[2] = v.y; rp[3] = v.z; rp[4] = v.w;
        rp[0] = (ix0 > 0)          ? __ldg(rowp + ix0 - 1) : 0.f;
        rp[5] = (ix0 + 4 < W_IN)   ? __ldg(rowp + ix0 + 4) : 0.f;
    } else {
        #pragma unroll
        for (int i = 0; i < 6; i++) rp[i] = 0.f;
    }

    // Compute 2 output rows x 8 output cols.
    // Local index lj = j+1 corresponds to input col c = ix0 + j.
    float oe[8], oo[8];
    #pragma unroll
    for (int j = 0; j < 4; j++) {
        int lj = j + 1;
        // out row 2*iy (even vertical phase: K[3]*row(iy-1) + K[1]*row(iy))
        oe[2*j]     = K33 * rm[lj-1] + K31 * rm[lj]
                    + K13 * rc[lj-1] + K11 * rc[lj];
        oe[2*j + 1] = K32 * rm[lj]   + K30 * rm[lj+1]
                    + K12 * rc[lj]   + K10 * rc[lj+1];
        // out row 2*iy+1 (odd vertical phase: K[2]*row(iy) + K[0]*row(iy+1))
        oo[2*j]     = K23 * rc[lj-1] + K21 * rc[lj]
                    + K03 * rp[lj-1] + K01 * rp[lj];
        oo[2*j + 1] = K22 * rc[lj]   + K20 * rc[lj+1]
                    + K02 * rp[lj]   + K00 * rp[lj+1];
    }

    int ox0 = 2 * ix0;  // multiple of 8 -> 32B-aligned float4 stores
    float* oe_p = op + (size_t)(2 * iy) * W_OUT + ox0;
    float* oo_p = op + (size_t)(2 * iy + 1) * W_OUT + ox0;
    *reinterpret_cast<float4*>(oe_p)     = make_float4(oe[0], oe[1], oe[2], oe[3]);
    *reinterpret_cast<float4*>(oe_p + 4) = make_float4(oe[4], oe[5], oe[6], oe[7]);
    *reinterpret_cast<float4*>(oo_p)     = make_float4(oo[0], oo[1], oo[2], oo[3]);
    *reinterpret_cast<float4*>(oo_p + 4) = make_float4(oo[4], oo[5], oo[6], oo[7]);
}

extern "C" void kernel_launch(void* const* d_in, const int* in_sizes, int n_in,
                              void* d_out, int out_size) {
    const float* x = (const float*)d_in[0];   // (8,128,128,128)
    const float* k = (const float*)d_in[1];   // (4,4)
    float* out = (float*)d_out;               // (8,128,256,256)

    // total threads = NC * H_IN * (W_IN/4) = 1024 * 128 * 32 = 4,194,304
    int threads = 256;
    int blocks = (NC * H_IN * (W_IN / 4)) / threads;  // 16384
    Upscale_15358803050749_kernel<<<blocks, threads>>>(x, k, out);
}